// round 16
// baseline (speedup 1.0000x reference)
#include <cuda_runtime.h>
#include <cuda_bf16.h>
#include <math.h>
#include <stdint.h>

#define BSZ    8192
#define DDIM   1024
#define D2     512
#define NH     2048
#define FSTEPS 8

// ---------------- scratch (__device__ globals; allocation-free rule) -------
__device__ __nv_bfloat16 g_xb[(size_t)BSZ * DDIM];    // x as bf16 (exact ints)
__device__ __nv_bfloat16 g_z0[(size_t)BSZ * DDIM];
__device__ __nv_bfloat16 g_z1[(size_t)BSZ * DDIM];
__device__ __nv_bfloat16 g_h1h[(size_t)BSZ * NH];
__device__ __nv_bfloat16 g_h1l[(size_t)BSZ * NH];
__device__ __nv_bfloat16 g_h2h[(size_t)BSZ * NH];
__device__ __nv_bfloat16 g_h2l[(size_t)BSZ * NH];
__device__ double g_partial[1024];
// transposed + split weights: Bt[f][n][k] (bf16 hi / lo)
__device__ __nv_bfloat16 g_w1_hi[(size_t)FSTEPS * NH * D2];
__device__ __nv_bfloat16 g_w1_lo[(size_t)FSTEPS * NH * D2];
__device__ __nv_bfloat16 g_w2_hi[(size_t)FSTEPS * NH * NH];
__device__ __nv_bfloat16 g_w2_lo[(size_t)FSTEPS * NH * NH];
__device__ __nv_bfloat16 g_w3_hi[(size_t)FSTEPS * D2 * NH];
__device__ __nv_bfloat16 g_w3_lo[(size_t)FSTEPS * D2 * NH];

// ---------------- helpers ---------------------------------------------------
__device__ __forceinline__ float lrelu(float x) { return fmaxf(x, 0.01f * x); }

__device__ __forceinline__ float logsigf(float x) {
    if (x >= 0.0f) return -log1pf(expf(-x));
    return x - log1pf(expf(x));
}

__device__ __forceinline__ uint32_t smem_u32(const void* p) {
    uint32_t a;
    asm("{ .reg .u64 t; cvta.to.shared.u64 t, %1; cvt.u32.u64 %0, t; }"
        : "=r"(a) : "l"(p));
    return a;
}

#define CP_ASYNC16(s, g) \
    asm volatile("cp.async.cg.shared.global [%0], [%1], 16;" :: "r"(s), "l"(g) : "memory")
#define CP_COMMIT() asm volatile("cp.async.commit_group;" ::: "memory")
#define CP_WAIT(N)  asm volatile("cp.async.wait_group %0;" :: "n"(N) : "memory")

#define LDSM4(r0, r1, r2, r3, addr) \
    asm volatile("ldmatrix.sync.aligned.m8n8.x4.shared.b16 {%0,%1,%2,%3}, [%4];" \
        : "=r"(r0), "=r"(r1), "=r"(r2), "=r"(r3) : "r"(addr))

#define MMA16816(c, a, b0, b1) \
    asm volatile("mma.sync.aligned.m16n8k16.row.col.f32.bf16.bf16.f32 " \
        "{%0,%1,%2,%3}, {%4,%5,%6,%7}, {%8,%9}, {%0,%1,%2,%3};" \
        : "+f"((c)[0]), "+f"((c)[1]), "+f"((c)[2]), "+f"((c)[3]) \
        : "r"((a)[0]), "r"((a)[1]), "r"((a)[2]), "r"((a)[3]), "r"(b0), "r"(b1))

// ---------------- weight transpose + bf16 hi/lo split -----------------------
// W[f][K][Nn] (row-major) -> Bt_hi/lo[f][Nn][K]
__global__ __launch_bounds__(1024)
void convW_kernel(const float* __restrict__ W,
                  __nv_bfloat16* __restrict__ Bhi,
                  __nv_bfloat16* __restrict__ Blo,
                  int K, int Nn)
{
    __shared__ float t[32][33];
    const int f = blockIdx.z;
    const float* Wf = W + (size_t)f * K * Nn;
    __nv_bfloat16* Hf = Bhi + (size_t)f * K * Nn;
    __nv_bfloat16* Lf = Blo + (size_t)f * K * Nn;
    const int tx = threadIdx.x, ty = threadIdx.y;
    const int k0 = blockIdx.y * 32, n0 = blockIdx.x * 32;
    t[ty][tx] = Wf[(size_t)(k0 + ty) * Nn + n0 + tx];
    __syncthreads();
    const float v = t[tx][ty];
    const __nv_bfloat16 hi = __float2bfloat16(v);
    const __nv_bfloat16 lo = __float2bfloat16(v - __bfloat162float(hi));
    Hf[(size_t)(n0 + ty) * K + k0 + tx] = hi;
    Lf[(size_t)(n0 + ty) * K + k0 + tx] = lo;
}

// x fp32 (integers) -> bf16 (exact)
__global__ __launch_bounds__(256)
void convX_kernel(const float* __restrict__ x, __nv_bfloat16* __restrict__ o)
{
    const int i = blockIdx.x * 256 + threadIdx.x;   // i indexes float4
    const float4 v = ((const float4*)x)[i];
    ((__nv_bfloat162*)o)[i * 2 + 0] =
        __halves2bfloat162(__float2bfloat16(v.x), __float2bfloat16(v.y));
    ((__nv_bfloat162*)o)[i * 2 + 1] =
        __halves2bfloat162(__float2bfloat16(v.z), __float2bfloat16(v.w));
}

// ---------------- warp-mma GEMM ---------------------------------------------
// D[128x128] = A(bf16 hi[/lo], M x K, stride lda) * Bt(bf16 hi/lo, [Nn][K])^T
// TERMS==2: D = A*Bhi + A*Blo          (A exact, GEMM1)
// TERMS==3: D = Ahi*Bhi + Ahi*Blo + Alo*Bhi
// EPI 0: h = lrelu(acc + bias[n]); write split bf16 hi/lo to Chi/Clo
// EPI 1: coupling epilogue (bias + rint + reversal) on bf16 z buffers
// K-chunk 32, 3-stage cp.async pipeline, one barrier per chunk, 2 CTAs/SM.
// Tiles are 128 rows x 32 bf16 (64B rows), swizzle: unit u -> u ^ ((row>>1)&3).
template <int TERMS> struct StageCfg;
template <> struct StageCfg<2> {
    static constexpr int OB_HI = 8192,  BYTES = 24576;
};
template <> struct StageCfg<3> {
    static constexpr int OB_HI = 16384, BYTES = 32768;
};

template <int EPI, int TERMS>
__global__ __launch_bounds__(256, 2)
void mma_gemm(const __nv_bfloat16* __restrict__ Ahi_g,
              const __nv_bfloat16* __restrict__ Alo_g,
              int lda,
              const __nv_bfloat16* __restrict__ Bhi_g,
              const __nv_bfloat16* __restrict__ Blo_g,
              const float* __restrict__ bias,
              __nv_bfloat16* __restrict__ Chi,
              __nv_bfloat16* __restrict__ Clo,
              const __nv_bfloat16* __restrict__ Zin,
              __nv_bfloat16* __restrict__ Zout,
              int Nn, int K)
{
    constexpr int STG   = StageCfg<TERMS>::BYTES;
    constexpr int OB_HI = StageCfg<TERMS>::OB_HI;

    extern __shared__ char smem[];
    __shared__ float sbias[128];

    const uint32_t sbase = smem_u32(smem);
    const int tid = threadIdx.x;
    const int wid = tid >> 5, lid = tid & 31;
    const int bx = blockIdx.x, by = blockIdx.y;
    const int warp_m = wid & 1;     // rows warp_m*64 .. +63
    const int warp_n = wid >> 1;    // cols warp_n*32 .. +31

    if (tid < 128) sbias[tid] = bias[bx * 128 + tid];

    const __nv_bfloat16* Ahi = Ahi_g + (size_t)(by * 128) * lda;
    const __nv_bfloat16* Alo = (TERMS == 3) ? (Alo_g + (size_t)(by * 128) * lda) : nullptr;
    const __nv_bfloat16* Bhi = Bhi_g + (size_t)(bx * 128) * K;
    const __nv_bfloat16* Blo = Blo_g + (size_t)(bx * 128) * K;

    const int KT = K >> 5;            // 32-wide k-chunks

    // --- tile loader: 128 rows x 32 bf16 (64B rows), swizzled 16B units ---
    auto load_tile = [&](uint32_t soff, const __nv_bfloat16* g, int ld, int kc) {
#pragma unroll
        for (int i = 0; i < 2; ++i) {
            const int idx = (i << 8) + tid;          // 0..511
            const int row = idx >> 2, u = idx & 3;
            const uint32_t s = sbase + soff + row * 64 + ((u ^ ((row >> 1) & 3)) << 4);
            const __nv_bfloat16* gp = g + (size_t)row * ld + kc + (u << 3);
            CP_ASYNC16(s, gp);
        }
    };
    auto load_stage = [&](int st, int kt) {
        const int kc = kt << 5;
        const uint32_t so = (uint32_t)st * STG;
        load_tile(so + 0, Ahi, lda, kc);
        if (TERMS == 3) load_tile(so + 8192, Alo, lda, kc);
        load_tile(so + OB_HI,        Bhi, K, kc);
        load_tile(so + OB_HI + 8192, Blo, K, kc);
        CP_COMMIT();
    };

    // --- per-lane ldmatrix address pieces ---
    const int rsub  = lid & 7;
    const int a_roff = rsub + (((lid >> 3) & 1) << 3);
    const int a_ub   = (lid >> 4) & 1;
    const int b_roff = rsub + (((lid >> 4) & 1) << 3);
    const int b_ub   = (lid >> 3) & 1;

    int aRowB[4], aSwz[4];
#pragma unroll
    for (int mt = 0; mt < 4; ++mt) {
        const int r = warp_m * 64 + mt * 16 + a_roff;
        aRowB[mt] = r * 64; aSwz[mt] = (r >> 1) & 3;
    }
    int bRowB[2], bSwz[2];
#pragma unroll
    for (int ng = 0; ng < 2; ++ng) {
        const int r = warp_n * 32 + ng * 16 + b_roff;
        bRowB[ng] = r * 64; bSwz[ng] = (r >> 1) & 3;
    }

    float acc[4][4][4];
#pragma unroll
    for (int mt = 0; mt < 4; ++mt)
#pragma unroll
        for (int nt = 0; nt < 4; ++nt)
#pragma unroll
            for (int q = 0; q < 4; ++q) acc[mt][nt][q] = 0.0f;

    // --- 3-stage pipeline, one barrier per chunk ---
    load_stage(0, 0);
    load_stage(1, 1);

    int slot = 0;          // slot of chunk kt (cycles 0,1,2)
    int wslot = 2;         // slot for chunk kt+2
    for (int kt = 0; kt < KT; ++kt) {
        if (kt < KT - 1) { CP_WAIT(1); } else { CP_WAIT(0); }
        __syncthreads();   // publish stage kt; proves slot(kt-1)==wslot is drained

        if (kt + 2 < KT) load_stage(wslot, kt + 2);

        const uint32_t so = sbase + (uint32_t)slot * STG;
#pragma unroll
        for (int kk = 0; kk < 2; ++kk) {
            // B fragments (hi + lo) for this k-step
            uint32_t bh[2][4], bl[2][4];
#pragma unroll
            for (int ng = 0; ng < 2; ++ng) {
                const int u = (kk << 1) + b_ub;
                const uint32_t bd = so + OB_HI + bRowB[ng] + ((u ^ bSwz[ng]) << 4);
                LDSM4(bh[ng][0], bh[ng][1], bh[ng][2], bh[ng][3], bd);
                LDSM4(bl[ng][0], bl[ng][1], bl[ng][2], bl[ng][3], bd + 8192);
            }
            // A fragments loaded per mt to bound register liveness
#pragma unroll
            for (int mt = 0; mt < 4; ++mt) {
                const int u = (kk << 1) + a_ub;
                const uint32_t ad = so + aRowB[mt] + ((u ^ aSwz[mt]) << 4);
                uint32_t ah[4], al[4];
                LDSM4(ah[0], ah[1], ah[2], ah[3], ad);
                if (TERMS == 3) { LDSM4(al[0], al[1], al[2], al[3], ad + 8192); }
#pragma unroll
                for (int nt = 0; nt < 4; ++nt) {
                    const int ng = nt >> 1, h = (nt & 1) << 1;
                    MMA16816(acc[mt][nt], ah, bh[ng][h], bh[ng][h + 1]);
                    MMA16816(acc[mt][nt], ah, bl[ng][h], bl[ng][h + 1]);
                    if (TERMS == 3)
                        MMA16816(acc[mt][nt], al, bh[ng][h], bh[ng][h + 1]);
                }
            }
        }

        slot  = (slot == 2)  ? 0 : slot + 1;
        wslot = (wslot == 2) ? 0 : wslot + 1;
    }

    // --- epilogue ---
    const int quad = lid >> 2, t4 = lid & 3;
#pragma unroll
    for (int mt = 0; mt < 4; ++mt) {
        const int r0 = by * 128 + warp_m * 64 + mt * 16 + quad;
#pragma unroll
        for (int nt = 0; nt < 4; ++nt) {
            const int lc = warp_n * 32 + nt * 8 + t4 * 2;
            const int gc = bx * 128 + lc;
            const float* a = acc[mt][nt];
            if (EPI == 0) {
#pragma unroll
                for (int rr = 0; rr < 2; ++rr) {
                    const float v0 = lrelu(a[rr * 2 + 0] + sbias[lc]);
                    const float v1 = lrelu(a[rr * 2 + 1] + sbias[lc + 1]);
                    const __nv_bfloat16 h0 = __float2bfloat16(v0);
                    const __nv_bfloat16 h1 = __float2bfloat16(v1);
                    const __nv_bfloat16 l0 = __float2bfloat16(v0 - __bfloat162float(h0));
                    const __nv_bfloat16 l1 = __float2bfloat16(v1 - __bfloat162float(h1));
                    const size_t off = (size_t)(r0 + rr * 8) * Nn + gc;
                    *(__nv_bfloat162*)(Chi + off) = __halves2bfloat162(h0, h1);
                    *(__nv_bfloat162*)(Clo + off) = __halves2bfloat162(l0, l1);
                }
            } else {
#pragma unroll
                for (int rr = 0; rr < 2; ++rr) {
                    const int r = r0 + rr * 8;
                    const size_t zr = (size_t)r * DDIM;
                    const int n = gc;   // 0..510, even
                    const __nv_bfloat162 xa2 = *(const __nv_bfloat162*)(Zin + zr + n);
                    const __nv_bfloat162 xb2 = *(const __nv_bfloat162*)(Zin + zr + D2 + n);
                    const float t0 = a[rr * 2 + 0] + sbias[lc];
                    const float t1 = a[rr * 2 + 1] + sbias[lc + 1];
                    const float yb0 = __bfloat162float(xb2.x) + rintf(t0);
                    const float yb1 = __bfloat162float(xb2.y) + rintf(t1);
                    // reversed: index D2-1-n holds yb(n); pack pairs descending
                    *(__nv_bfloat162*)(Zout + zr + (D2 - 2 - n)) =
                        __halves2bfloat162(__float2bfloat16(yb1), __float2bfloat16(yb0));
                    *(__nv_bfloat162*)(Zout + zr + (DDIM - 2 - n)) =
                        __halves2bfloat162(xa2.y, xa2.x);
                }
            }
        }
    }
}

// ---------------- final log-prob reduction ----------------------------------
__global__ __launch_bounds__(256)
void logp_kernel(const __nv_bfloat16* __restrict__ Z,
                 const float* __restrict__ mean,
                 const float* __restrict__ logscale)
{
    __shared__ double sred[256];
    const int b   = blockIdx.x;
    const int tid = threadIdx.x;
    const size_t base = (size_t)b * 8 * DDIM;

    double s = 0.0;
    for (int idx = tid; idx < 8 * DDIM; idx += 256) {
        const int d = idx & (DDIM - 1);
        const float z  = __bfloat162float(Z[base + idx]);
        const float sc = expf(logscale[d]);
        const float m  = mean[d];
        const float la = logsigf((z + 0.5f - m) / sc);
        const float lb = logsigf((z - 0.5f - m) / sc);
        const float lp = la + logf(1.0f - expf(lb - la) + 1e-8f);
        s += (double)lp;
    }
    sred[tid] = s;
    __syncthreads();
#pragma unroll
    for (int off = 128; off > 0; off >>= 1) {
        if (tid < off) sred[tid] += sred[tid + off];
        __syncthreads();
    }
    if (tid == 0) g_partial[b] = sred[0];
}

__global__ __launch_bounds__(256)
void finalize_kernel(float* __restrict__ out)
{
    __shared__ double sred[256];
    const int tid = threadIdx.x;
    double s = 0.0;
    for (int i = tid; i < 1024; i += 256) s += g_partial[i];
    sred[tid] = s;
    __syncthreads();
#pragma unroll
    for (int off = 128; off > 0; off >>= 1) {
        if (tid < off) sred[tid] += sred[tid + off];
        __syncthreads();
    }
    if (tid == 0) out[0] = (float)(-sred[0] / (double)BSZ);
}

// ---------------------------------------------------------------------------
extern "C" void kernel_launch(void* const* d_in, const int* in_sizes, int n_in,
                              void* d_out, int out_size)
{
    const float* x        = (const float*)d_in[0];
    const float* W1       = (const float*)d_in[1];
    const float* b1       = (const float*)d_in[2];
    const float* W2       = (const float*)d_in[3];
    const float* b2       = (const float*)d_in[4];
    const float* W3       = (const float*)d_in[5];
    const float* b3       = (const float*)d_in[6];
    const float* mean     = (const float*)d_in[7];
    const float* logscale = (const float*)d_in[8];

    __nv_bfloat16 *xb, *z0, *z1, *h1h, *h1l, *h2h, *h2l;
    cudaGetSymbolAddress((void**)&xb,  g_xb);
    cudaGetSymbolAddress((void**)&z0,  g_z0);
    cudaGetSymbolAddress((void**)&z1,  g_z1);
    cudaGetSymbolAddress((void**)&h1h, g_h1h);
    cudaGetSymbolAddress((void**)&h1l, g_h1l);
    cudaGetSymbolAddress((void**)&h2h, g_h2h);
    cudaGetSymbolAddress((void**)&h2l, g_h2l);
    __nv_bfloat16 *w1h, *w1l, *w2h, *w2l, *w3h, *w3l;
    cudaGetSymbolAddress((void**)&w1h, g_w1_hi);
    cudaGetSymbolAddress((void**)&w1l, g_w1_lo);
    cudaGetSymbolAddress((void**)&w2h, g_w2_hi);
    cudaGetSymbolAddress((void**)&w2l, g_w2_lo);
    cudaGetSymbolAddress((void**)&w3h, g_w3_hi);
    cudaGetSymbolAddress((void**)&w3l, g_w3_lo);

    const int SMEM2 = 3 * StageCfg<2>::BYTES;   // 72 KB -> 2 CTAs/SM
    const int SMEM3 = 3 * StageCfg<3>::BYTES;   // 96 KB -> 2 CTAs/SM
    cudaFuncSetAttribute(mma_gemm<0, 2>, cudaFuncAttributeMaxDynamicSharedMemorySize, SMEM2);
    cudaFuncSetAttribute(mma_gemm<0, 3>, cudaFuncAttributeMaxDynamicSharedMemorySize, SMEM3);
    cudaFuncSetAttribute(mma_gemm<1, 3>, cudaFuncAttributeMaxDynamicSharedMemorySize, SMEM3);

    // weight transpose + bf16 split, all steps
    convW_kernel<<<dim3(NH / 32, D2 / 32, FSTEPS), dim3(32, 32)>>>(W1, w1h, w1l, D2, NH);
    convW_kernel<<<dim3(NH / 32, NH / 32, FSTEPS), dim3(32, 32)>>>(W2, w2h, w2l, NH, NH);
    convW_kernel<<<dim3(D2 / 32, NH / 32, FSTEPS), dim3(32, 32)>>>(W3, w3h, w3l, NH, D2);
    convX_kernel<<<(BSZ * DDIM / 4) / 256, 256>>>(x, xb);

    const dim3 block(256);
    const dim3 grid12(NH / 128, BSZ / 128);   // (16, 64)
    const dim3 grid3 (D2 / 128, BSZ / 128);   // (4, 64)

    for (int f = 0; f < FSTEPS; ++f) {
        const __nv_bfloat16* zin = (f == 0) ? xb : ((f & 1) ? z0 : z1);
        __nv_bfloat16* zout = (f & 1) ? z1 : z0;

        const __nv_bfloat16* w1hf = w1h + (size_t)f * NH * D2;
        const __nv_bfloat16* w1lf = w1l + (size_t)f * NH * D2;
        const __nv_bfloat16* w2hf = w2h + (size_t)f * NH * NH;
        const __nv_bfloat16* w2lf = w2l + (size_t)f * NH * NH;
        const __nv_bfloat16* w3hf = w3h + (size_t)f * D2 * NH;
        const __nv_bfloat16* w3lf = w3l + (size_t)f * D2 * NH;
        const float* b1f = b1 + (size_t)f * NH;
        const float* b2f = b2 + (size_t)f * NH;
        const float* b3f = b3 + (size_t)f * D2;

        // h1 = lrelu(xa @ W1 + b1); A = z (exact bf16) -> 2 terms
        mma_gemm<0, 2><<<grid12, block, SMEM2>>>(zin, nullptr, DDIM,
                                                 w1hf, w1lf, b1f,
                                                 h1h, h1l, nullptr, nullptr, NH, D2);
        // h2 = lrelu(h1 @ W2 + b2); 3 terms
        mma_gemm<0, 3><<<grid12, block, SMEM3>>>(h1h, h1l, NH,
                                                 w2hf, w2lf, b2f,
                                                 h2h, h2l, nullptr, nullptr, NH, NH);
        // t = h2 @ W3 + b3; coupling + reversal fused; 3 terms
        mma_gemm<1, 3><<<grid3, block, SMEM3>>>(h2h, h2l, NH,
                                                w3hf, w3lf, b3f,
                                                nullptr, nullptr, zin, zout, D2, NH);
    }

    logp_kernel<<<1024, block>>>(z1, mean, logscale);
    finalize_kernel<<<1, block>>>((float*)d_out);
}

// round 17
// speedup vs baseline: 1.3595x; 1.3595x over previous
#include <cuda_runtime.h>
#include <cuda_fp16.h>
#include <math.h>
#include <stdint.h>

#define BSZ    8192
#define DDIM   1024
#define D2     512
#define NH     2048
#define FSTEPS 8

// ---------------- scratch (__device__ globals; allocation-free rule) -------
__device__ __half g_xh[(size_t)BSZ * DDIM];    // x as fp16 (exact ints)
__device__ __half g_z0[(size_t)BSZ * DDIM];
__device__ __half g_z1[(size_t)BSZ * DDIM];
__device__ __half g_h1[(size_t)BSZ * NH];
__device__ __half g_h2[(size_t)BSZ * NH];
__device__ double g_partial[1024];
// transposed + split weights: Bt[f][n][k] (fp16 hi / lo)
__device__ __half g_w1_hi[(size_t)FSTEPS * NH * D2];
__device__ __half g_w1_lo[(size_t)FSTEPS * NH * D2];
__device__ __half g_w2_hi[(size_t)FSTEPS * NH * NH];
__device__ __half g_w2_lo[(size_t)FSTEPS * NH * NH];
__device__ __half g_w3_hi[(size_t)FSTEPS * D2 * NH];
__device__ __half g_w3_lo[(size_t)FSTEPS * D2 * NH];

// ---------------- helpers ---------------------------------------------------
__device__ __forceinline__ float lrelu(float x) { return fmaxf(x, 0.01f * x); }

__device__ __forceinline__ float logsigf(float x) {
    if (x >= 0.0f) return -log1pf(expf(-x));
    return x - log1pf(expf(x));
}

__device__ __forceinline__ uint32_t smem_u32(const void* p) {
    uint32_t a;
    asm("{ .reg .u64 t; cvta.to.shared.u64 t, %1; cvt.u32.u64 %0, t; }"
        : "=r"(a) : "l"(p));
    return a;
}

#define CP_ASYNC16(s, g) \
    asm volatile("cp.async.cg.shared.global [%0], [%1], 16;" :: "r"(s), "l"(g) : "memory")
#define CP_COMMIT() asm volatile("cp.async.commit_group;" ::: "memory")
#define CP_WAIT(N)  asm volatile("cp.async.wait_group %0;" :: "n"(N) : "memory")

#define LDSM4(r0, r1, r2, r3, addr) \
    asm volatile("ldmatrix.sync.aligned.m8n8.x4.shared.b16 {%0,%1,%2,%3}, [%4];" \
        : "=r"(r0), "=r"(r1), "=r"(r2), "=r"(r3) : "r"(addr))

#define MMA16816(c, a, b0, b1) \
    asm volatile("mma.sync.aligned.m16n8k16.row.col.f32.f16.f16.f32 " \
        "{%0,%1,%2,%3}, {%4,%5,%6,%7}, {%8,%9}, {%0,%1,%2,%3};" \
        : "+f"((c)[0]), "+f"((c)[1]), "+f"((c)[2]), "+f"((c)[3]) \
        : "r"((a)[0]), "r"((a)[1]), "r"((a)[2]), "r"((a)[3]), "r"(b0), "r"(b1))

// ---------------- weight transpose + fp16 hi/lo split -----------------------
// W[f][K][Nn] (row-major) -> Bt_hi/lo[f][Nn][K]
__global__ __launch_bounds__(1024)
void convW_kernel(const float* __restrict__ W,
                  __half* __restrict__ Bhi,
                  __half* __restrict__ Blo,
                  int K, int Nn)
{
    __shared__ float t[32][33];
    const int f = blockIdx.z;
    const float* Wf = W + (size_t)f * K * Nn;
    __half* Hf = Bhi + (size_t)f * K * Nn;
    __half* Lf = Blo + (size_t)f * K * Nn;
    const int tx = threadIdx.x, ty = threadIdx.y;
    const int k0 = blockIdx.y * 32, n0 = blockIdx.x * 32;
    t[ty][tx] = Wf[(size_t)(k0 + ty) * Nn + n0 + tx];
    __syncthreads();
    const float v = t[tx][ty];
    const __half hi = __float2half(v);
    const __half lo = __float2half(v - __half2float(hi));
    Hf[(size_t)(n0 + ty) * K + k0 + tx] = hi;
    Lf[(size_t)(n0 + ty) * K + k0 + tx] = lo;
}

// x fp32 (integers, |x| small) -> fp16 (exact)
__global__ __launch_bounds__(256)
void convX_kernel(const float* __restrict__ x, __half* __restrict__ o)
{
    const int i = blockIdx.x * 256 + threadIdx.x;   // i indexes float4
    const float4 v = ((const float4*)x)[i];
    ((__half2*)o)[i * 2 + 0] = __floats2half2_rn(v.x, v.y);
    ((__half2*)o)[i * 2 + 1] = __floats2half2_rn(v.z, v.w);
}

// ---------------- warp-mma GEMM ---------------------------------------------
// D[128x128] = A(fp16, M x K, stride lda) * Bt(fp16 hi/lo, [Nn][K])^T
// Always 2 MMA terms: D = A*Bhi + A*Blo (weight split covers fp32 precision;
// activation quantization error is the fp16 rounding of A, ~2^-12 relative).
// EPI 0: C[r][n] = fp16(lrelu(acc + bias[n]))
// EPI 1: coupling epilogue (bias + rint + reversal) on fp16 z buffers
// K-chunk 64, 3-stage cp.async pipeline, one barrier per chunk.
static constexpr int OB_HI = 16384;
static constexpr int STG   = 49152;            // A + Bhi + Blo, 16KB each

template <int EPI>
__global__ __launch_bounds__(256, 1)
void mma_gemm(const __half* __restrict__ A_g, int lda,
              const __half* __restrict__ Bhi_g,
              const __half* __restrict__ Blo_g,
              const float* __restrict__ bias,
              __half* __restrict__ C,
              const __half* __restrict__ Zin,
              __half* __restrict__ Zout,
              int Nn, int K)
{
    extern __shared__ char smem[];
    __shared__ float sbias[128];

    const uint32_t sbase = smem_u32(smem);
    const int tid = threadIdx.x;
    const int wid = tid >> 5, lid = tid & 31;
    const int bx = blockIdx.x, by = blockIdx.y;
    const int warp_m = wid & 1;     // rows warp_m*64 .. +63
    const int warp_n = wid >> 1;    // cols warp_n*32 .. +31

    if (tid < 128) sbias[tid] = bias[bx * 128 + tid];

    const __half* A   = A_g   + (size_t)(by * 128) * lda;
    const __half* Bhi = Bhi_g + (size_t)(bx * 128) * K;
    const __half* Blo = Blo_g + (size_t)(bx * 128) * K;

    const int KT = K >> 6;

    // --- tile loader: 128 rows x 64 fp16, XOR-swizzled 16B units ---
    auto load_tile = [&](uint32_t soff, const __half* g, int ld, int kc) {
#pragma unroll
        for (int i = 0; i < 4; ++i) {
            const int idx = (i << 8) + tid;          // 0..1023
            const int row = idx >> 3, u = idx & 7;
            const uint32_t s = sbase + soff + row * 128 + ((u ^ (row & 7)) << 4);
            const __half* gp = g + (size_t)row * ld + kc + (u << 3);
            CP_ASYNC16(s, gp);
        }
    };
    auto load_stage = [&](int st, int kt) {
        const int kc = kt << 6;
        const uint32_t so = (uint32_t)st * STG;
        load_tile(so + 0,              A,   lda, kc);
        load_tile(so + OB_HI,          Bhi, K,   kc);
        load_tile(so + OB_HI + 16384,  Blo, K,   kc);
        CP_COMMIT();
    };

    // --- per-lane ldmatrix address pieces ---
    const int rsub  = lid & 7;
    const int a_roff = rsub + (((lid >> 3) & 1) << 3);
    const int a_ub   = (lid >> 4) & 1;
    const int b_roff = rsub + (((lid >> 4) & 1) << 3);
    const int b_ub   = (lid >> 3) & 1;

    int aRowB[4], aSw7[4];
#pragma unroll
    for (int mt = 0; mt < 4; ++mt) {
        const int r = warp_m * 64 + mt * 16 + a_roff;
        aRowB[mt] = r * 128; aSw7[mt] = r & 7;
    }
    int bRowB[2], bSw7[2];
#pragma unroll
    for (int ng = 0; ng < 2; ++ng) {
        const int r = warp_n * 32 + ng * 16 + b_roff;
        bRowB[ng] = r * 128; bSw7[ng] = r & 7;
    }

    float acc[4][4][4];
#pragma unroll
    for (int mt = 0; mt < 4; ++mt)
#pragma unroll
        for (int nt = 0; nt < 4; ++nt)
#pragma unroll
            for (int q = 0; q < 4; ++q) acc[mt][nt][q] = 0.0f;

    // --- 3-stage pipeline, one barrier per chunk ---
    load_stage(0, 0);
    load_stage(1, 1);

    int slot = 0, wslot = 2;
    for (int kt = 0; kt < KT; ++kt) {
        if (kt < KT - 1) { CP_WAIT(1); } else { CP_WAIT(0); }
        __syncthreads();   // publish stage kt; proves slot(kt-1)==wslot drained

        if (kt + 2 < KT) load_stage(wslot, kt + 2);

        const uint32_t so = sbase + (uint32_t)slot * STG;
#pragma unroll
        for (int kk = 0; kk < 4; ++kk) {
            uint32_t ah[4][4];
#pragma unroll
            for (int mt = 0; mt < 4; ++mt) {
                const int u = (kk << 1) + a_ub;
                const uint32_t ad = so + aRowB[mt] + ((u ^ aSw7[mt]) << 4);
                LDSM4(ah[mt][0], ah[mt][1], ah[mt][2], ah[mt][3], ad);
            }
            uint32_t bh[2][4], bl[2][4];
#pragma unroll
            for (int ng = 0; ng < 2; ++ng) {
                const int u = (kk << 1) + b_ub;
                const uint32_t bd = so + OB_HI + bRowB[ng] + ((u ^ bSw7[ng]) << 4);
                LDSM4(bh[ng][0], bh[ng][1], bh[ng][2], bh[ng][3], bd);
                LDSM4(bl[ng][0], bl[ng][1], bl[ng][2], bl[ng][3], bd + 16384);
            }
#pragma unroll
            for (int mt = 0; mt < 4; ++mt)
#pragma unroll
                for (int nt = 0; nt < 4; ++nt) {
                    const int ng = nt >> 1, h = (nt & 1) << 1;
                    MMA16816(acc[mt][nt], ah[mt], bh[ng][h], bh[ng][h + 1]);
                    MMA16816(acc[mt][nt], ah[mt], bl[ng][h], bl[ng][h + 1]);
                }
        }

        slot  = (slot == 2)  ? 0 : slot + 1;
        wslot = (wslot == 2) ? 0 : wslot + 1;
    }

    // --- epilogue ---
    const int quad = lid >> 2, t4 = lid & 3;
#pragma unroll
    for (int mt = 0; mt < 4; ++mt) {
        const int r0 = by * 128 + warp_m * 64 + mt * 16 + quad;
#pragma unroll
        for (int nt = 0; nt < 4; ++nt) {
            const int lc = warp_n * 32 + nt * 8 + t4 * 2;
            const int gc = bx * 128 + lc;
            const float* a = acc[mt][nt];
            if (EPI == 0) {
#pragma unroll
                for (int rr = 0; rr < 2; ++rr) {
                    const float v0 = lrelu(a[rr * 2 + 0] + sbias[lc]);
                    const float v1 = lrelu(a[rr * 2 + 1] + sbias[lc + 1]);
                    const size_t off = (size_t)(r0 + rr * 8) * Nn + gc;
                    *(__half2*)(C + off) = __floats2half2_rn(v0, v1);
                }
            } else {
#pragma unroll
                for (int rr = 0; rr < 2; ++rr) {
                    const int r = r0 + rr * 8;
                    const size_t zr = (size_t)r * DDIM;
                    const int n = gc;   // 0..510, even
                    const __half2 xa2 = *(const __half2*)(Zin + zr + n);
                    const __half2 xb2 = *(const __half2*)(Zin + zr + D2 + n);
                    const float t0 = a[rr * 2 + 0] + sbias[lc];
                    const float t1 = a[rr * 2 + 1] + sbias[lc + 1];
                    const float yb0 = __half2float(__low2half(xb2))  + rintf(t0);
                    const float yb1 = __half2float(__high2half(xb2)) + rintf(t1);
                    // reversed: index D2-1-n holds yb(n); pack pairs descending
                    *(__half2*)(Zout + zr + (D2 - 2 - n)) = __floats2half2_rn(yb1, yb0);
                    *(__half2*)(Zout + zr + (DDIM - 2 - n)) =
                        __halves2half2(__high2half(xa2), __low2half(xa2));
                }
            }
        }
    }
}

// ---------------- final log-prob reduction ----------------------------------
__global__ __launch_bounds__(256)
void logp_kernel(const __half* __restrict__ Z,
                 const float* __restrict__ mean,
                 const float* __restrict__ logscale)
{
    __shared__ double sred[256];
    const int b   = blockIdx.x;
    const int tid = threadIdx.x;
    const size_t base = (size_t)b * 8 * DDIM;

    double s = 0.0;
    for (int idx = tid; idx < 8 * DDIM; idx += 256) {
        const int d = idx & (DDIM - 1);
        const float z  = __half2float(Z[base + idx]);
        const float sc = expf(logscale[d]);
        const float m  = mean[d];
        const float la = logsigf((z + 0.5f - m) / sc);
        const float lb = logsigf((z - 0.5f - m) / sc);
        const float lp = la + logf(1.0f - expf(lb - la) + 1e-8f);
        s += (double)lp;
    }
    sred[tid] = s;
    __syncthreads();
#pragma unroll
    for (int off = 128; off > 0; off >>= 1) {
        if (tid < off) sred[tid] += sred[tid + off];
        __syncthreads();
    }
    if (tid == 0) g_partial[b] = sred[0];
}

__global__ __launch_bounds__(256)
void finalize_kernel(float* __restrict__ out)
{
    __shared__ double sred[256];
    const int tid = threadIdx.x;
    double s = 0.0;
    for (int i = tid; i < 1024; i += 256) s += g_partial[i];
    sred[tid] = s;
    __syncthreads();
#pragma unroll
    for (int off = 128; off > 0; off >>= 1) {
        if (tid < off) sred[tid] += sred[tid + off];
        __syncthreads();
    }
    if (tid == 0) out[0] = (float)(-sred[0] / (double)BSZ);
}

// ---------------------------------------------------------------------------
extern "C" void kernel_launch(void* const* d_in, const int* in_sizes, int n_in,
                              void* d_out, int out_size)
{
    const float* x        = (const float*)d_in[0];
    const float* W1       = (const float*)d_in[1];
    const float* b1       = (const float*)d_in[2];
    const float* W2       = (const float*)d_in[3];
    const float* b2       = (const float*)d_in[4];
    const float* W3       = (const float*)d_in[5];
    const float* b3       = (const float*)d_in[6];
    const float* mean     = (const float*)d_in[7];
    const float* logscale = (const float*)d_in[8];

    __half *xh, *z0, *z1, *h1, *h2;
    cudaGetSymbolAddress((void**)&xh, g_xh);
    cudaGetSymbolAddress((void**)&z0, g_z0);
    cudaGetSymbolAddress((void**)&z1, g_z1);
    cudaGetSymbolAddress((void**)&h1, g_h1);
    cudaGetSymbolAddress((void**)&h2, g_h2);
    __half *w1h, *w1l, *w2h, *w2l, *w3h, *w3l;
    cudaGetSymbolAddress((void**)&w1h, g_w1_hi);
    cudaGetSymbolAddress((void**)&w1l, g_w1_lo);
    cudaGetSymbolAddress((void**)&w2h, g_w2_hi);
    cudaGetSymbolAddress((void**)&w2l, g_w2_lo);
    cudaGetSymbolAddress((void**)&w3h, g_w3_hi);
    cudaGetSymbolAddress((void**)&w3l, g_w3_lo);

    const int SMEM = 3 * STG;   // 144 KB
    cudaFuncSetAttribute(mma_gemm<0>, cudaFuncAttributeMaxDynamicSharedMemorySize, SMEM);
    cudaFuncSetAttribute(mma_gemm<1>, cudaFuncAttributeMaxDynamicSharedMemorySize, SMEM);

    // weight transpose + fp16 split, all steps
    convW_kernel<<<dim3(NH / 32, D2 / 32, FSTEPS), dim3(32, 32)>>>(W1, w1h, w1l, D2, NH);
    convW_kernel<<<dim3(NH / 32, NH / 32, FSTEPS), dim3(32, 32)>>>(W2, w2h, w2l, NH, NH);
    convW_kernel<<<dim3(D2 / 32, NH / 32, FSTEPS), dim3(32, 32)>>>(W3, w3h, w3l, NH, D2);
    convX_kernel<<<(BSZ * DDIM / 4) / 256, 256>>>(x, xh);

    const dim3 block(256);
    const dim3 grid12(NH / 128, BSZ / 128);   // (16, 64)
    const dim3 grid3 (D2 / 128, BSZ / 128);   // (4, 64)

    for (int f = 0; f < FSTEPS; ++f) {
        const __half* zin = (f == 0) ? xh : ((f & 1) ? z0 : z1);
        __half* zout = (f & 1) ? z1 : z0;

        const __half* w1hf = w1h + (size_t)f * NH * D2;
        const __half* w1lf = w1l + (size_t)f * NH * D2;
        const __half* w2hf = w2h + (size_t)f * NH * NH;
        const __half* w2lf = w2l + (size_t)f * NH * NH;
        const __half* w3hf = w3h + (size_t)f * D2 * NH;
        const __half* w3lf = w3l + (size_t)f * D2 * NH;
        const float* b1f = b1 + (size_t)f * NH;
        const float* b2f = b2 + (size_t)f * NH;
        const float* b3f = b3 + (size_t)f * D2;

        // h1 = lrelu(xa @ W1 + b1); A = z exact fp16
        mma_gemm<0><<<grid12, block, SMEM>>>(zin, DDIM, w1hf, w1lf, b1f,
                                             h1, nullptr, nullptr, NH, D2);
        // h2 = lrelu(h1 @ W2 + b2)
        mma_gemm<0><<<grid12, block, SMEM>>>(h1, NH, w2hf, w2lf, b2f,
                                             h2, nullptr, nullptr, NH, NH);
        // t = h2 @ W3 + b3; coupling + reversal fused
        mma_gemm<1><<<grid3, block, SMEM>>>(h2, NH, w3hf, w3lf, b3f,
                                            nullptr, zin, zout, D2, NH);
    }

    logp_kernel<<<1024, block>>>(z1, mean, logscale);
    finalize_kernel<<<1, block>>>((float*)d_out);
}